// round 3
// baseline (speedup 1.0000x reference)
#include <cuda_runtime.h>
#include <stdint.h>

// Problem shapes (fixed by the reference setup_inputs):
//   ids_uid   : [4096, 200] int32
//   ids_item  : [4096, 50]  int32
//   table_uid : [1000000, 64]  float32
//   table_item: [100000, 128] float32
//   out       : [4096, 192] float32  (cols 0..63 = uid sum-pool, 64..191 = item mean-pool)
// PADDING_IDX = 0: rows with id==0 are masked out; mean denom clipped to >=1.

#define B        4096
#define L_UID    200
#define L_ITEM   50
#define D_UID    64
#define D_ITEM   128
#define D_OUT    192

__global__ __launch_bounds__(256, 8)
void sharded_emb_kernel(const int* __restrict__ ids_uid,
                        const int* __restrict__ ids_item,
                        const float* __restrict__ t_uid,
                        const float* __restrict__ t_item,
                        float* __restrict__ out)
{
    const int warp = (blockIdx.x * blockDim.x + threadIdx.x) >> 5;
    const int lane = threadIdx.x & 31;

    if (warp < B) {
        // ---------- uid: sum pooling, D=64, lane owns 2 consecutive floats ----------
        const int row = warp;
        const int* __restrict__ ids = ids_uid + row * L_UID;
        const int col = lane * 2;

        float ax = 0.f, ay = 0.f;

        #pragma unroll 4
        for (int i = 0; i < L_UID; ++i) {
            const int id = __ldg(ids + i);                 // broadcast across warp
            const float2 v = *reinterpret_cast<const float2*>(
                t_uid + (size_t)id * D_UID + col);
            const float m = (id != 0) ? 1.0f : 0.0f;       // padding mask, branchless
            ax = fmaf(m, v.x, ax);
            ay = fmaf(m, v.y, ay);
        }

        float2 r; r.x = ax; r.y = ay;
        *reinterpret_cast<float2*>(out + (size_t)row * D_OUT + col) = r;

    } else if (warp < 2 * B) {
        // ---------- item: mean pooling, D=128, lane owns 4 consecutive floats ----------
        const int row = warp - B;
        const int* __restrict__ ids = ids_item + row * L_ITEM;
        const int col = lane * 4;

        float ax = 0.f, ay = 0.f, az = 0.f, aw = 0.f;
        int cnt = 0;

        #pragma unroll 5
        for (int i = 0; i < L_ITEM; ++i) {
            const int id = __ldg(ids + i);
            const float4 v = *reinterpret_cast<const float4*>(
                t_item + (size_t)id * D_ITEM + col);
            const float m = (id != 0) ? 1.0f : 0.0f;
            cnt += (id != 0);
            ax = fmaf(m, v.x, ax);
            ay = fmaf(m, v.y, ay);
            az = fmaf(m, v.z, az);
            aw = fmaf(m, v.w, aw);
        }

        const float inv = 1.0f / (float)max(cnt, 1);       // clip denom to >= 1
        float4 r;
        r.x = ax * inv; r.y = ay * inv; r.z = az * inv; r.w = aw * inv;
        // offset (row*192 + 64 + lane*4) floats => 16B aligned (192, 64, 4*lane all /4)
        *reinterpret_cast<float4*>(out + (size_t)row * D_OUT + D_UID + col) = r;
    }
}

extern "C" void kernel_launch(void* const* d_in, const int* in_sizes, int n_in,
                              void* d_out, int out_size)
{
    (void)in_sizes; (void)n_in; (void)out_size;
    const int*   ids_uid  = (const int*)  d_in[0];
    const int*   ids_item = (const int*)  d_in[1];
    const float* t_uid    = (const float*)d_in[2];
    const float* t_item   = (const float*)d_in[3];
    float*       out      = (float*)d_out;

    // 2*B warps total, 8 warps (256 threads) per block -> 1024 blocks.
    const int warps_total = 2 * B;
    const int threads = 256;
    const int blocks = (warps_total * 32) / threads;   // 1024

    sharded_emb_kernel<<<blocks, threads>>>(ids_uid, ids_item, t_uid, t_item, out);
}

// round 4
// speedup vs baseline: 1.1513x; 1.1513x over previous
#include <cuda_runtime.h>
#include <stdint.h>

// Shapes (fixed by reference setup_inputs):
//   ids_uid   : [4096, 200] int32
//   ids_item  : [4096, 50]  int32
//   table_uid : [1000000, 64]  float32
//   table_item: [100000, 128] float32
//   out       : [4096, 192] float32 (cols 0..63 uid sum-pool, 64..191 item mean-pool)
// PADDING_IDX = 0; mean denom clipped to >= 1.

#define B        4096
#define L_UID    200
#define L_ITEM   50
#define D_UID    64
#define D_ITEM   128
#define D_OUT    192
#define UID_CHUNKS 4                  // 200 / 4 = 50 ids per chunk-warp
#define IDS_PER_CHUNK (L_UID / UID_CHUNKS)

// ---------------------------------------------------------------------------
// Kernel 1: zero the uid columns of out (output is poisoned; uid part is
// accumulated via atomics so it must start at 0; item part is stored with =).
// 4096 rows x 64 floats = 16 float4 per row -> 65536 threads.
// ---------------------------------------------------------------------------
__global__ __launch_bounds__(256)
void zero_uid_kernel(float* __restrict__ out)
{
    const int t   = blockIdx.x * blockDim.x + threadIdx.x;  // 0..65535
    const int row = t >> 4;
    const int q   = t & 15;
    *reinterpret_cast<float4*>(out + (size_t)row * D_OUT + q * 4) =
        make_float4(0.f, 0.f, 0.f, 0.f);
}

// ---------------------------------------------------------------------------
// Kernel 2: balanced gather/pool.
// Warps are organized in groups of 5 per output row:
//   k = 0..3 : uid chunk k (50 ids, partial sum, atomicAdd into out)
//   k = 4    : item row    (50 ids, mean, direct store)
// 4096 groups * 5 warps = 20480 warps = 2560 blocks of 8 warps.
// Every warp does ~50 gathers -> uniform work, no tail imbalance.
// ---------------------------------------------------------------------------
__global__ __launch_bounds__(256, 6)
void emb_pool_kernel(const int*   __restrict__ ids_uid,
                     const int*   __restrict__ ids_item,
                     const float* __restrict__ t_uid,
                     const float* __restrict__ t_item,
                     float*       __restrict__ out)
{
    const int gw   = (blockIdx.x * blockDim.x + threadIdx.x) >> 5;
    const int lane = threadIdx.x & 31;
    const int group = gw / 5;
    const int k     = gw - group * 5;
    if (group >= B) return;

    if (k < UID_CHUNKS) {
        // ----- uid partial: sum pool over 50 ids, lane owns 2 floats -----
        const int* __restrict__ ids = ids_uid + (size_t)group * L_UID + k * IDS_PER_CHUNK;
        const int col = lane * 2;

        float ax = 0.f, ay = 0.f;

        #pragma unroll 5
        for (int i = 0; i < IDS_PER_CHUNK; ++i) {
            const int id = __ldg(ids + i);                   // warp-broadcast
            const float2 v = *reinterpret_cast<const float2*>(
                t_uid + (size_t)id * D_UID + col);
            const float m = (id != 0) ? 1.0f : 0.0f;
            ax = fmaf(m, v.x, ax);
            ay = fmaf(m, v.y, ay);
        }

        float* dst = out + (size_t)group * D_OUT + col;
        atomicAdd(dst,     ax);                              // REDG.ADD.F32
        atomicAdd(dst + 1, ay);

    } else {
        // ----- item: mean pool over 50 ids, lane owns 4 floats -----
        const int* __restrict__ ids = ids_item + (size_t)group * L_ITEM;
        const int col = lane * 4;

        float ax = 0.f, ay = 0.f, az = 0.f, aw = 0.f;
        int cnt = 0;

        #pragma unroll 5
        for (int i = 0; i < L_ITEM; ++i) {
            const int id = __ldg(ids + i);
            const float4 v = *reinterpret_cast<const float4*>(
                t_item + (size_t)id * D_ITEM + col);
            const float m = (id != 0) ? 1.0f : 0.0f;
            cnt += (id != 0);
            ax = fmaf(m, v.x, ax);
            ay = fmaf(m, v.y, ay);
            az = fmaf(m, v.z, az);
            aw = fmaf(m, v.w, aw);
        }

        const float inv = 1.0f / (float)max(cnt, 1);
        float4 r;
        r.x = ax * inv; r.y = ay * inv; r.z = az * inv; r.w = aw * inv;
        *reinterpret_cast<float4*>(out + (size_t)group * D_OUT + D_UID + col) = r;
    }
}

extern "C" void kernel_launch(void* const* d_in, const int* in_sizes, int n_in,
                              void* d_out, int out_size)
{
    (void)in_sizes; (void)n_in; (void)out_size;
    const int*   ids_uid  = (const int*)  d_in[0];
    const int*   ids_item = (const int*)  d_in[1];
    const float* t_uid    = (const float*)d_in[2];
    const float* t_item   = (const float*)d_in[3];
    float*       out      = (float*)d_out;

    // Zero uid region: 65536 threads.
    zero_uid_kernel<<<256, 256>>>(out);

    // Main: 4096 groups * 5 warps = 20480 warps -> 2560 blocks of 256 threads.
    const int warps_total = B * (UID_CHUNKS + 1);
    const int blocks = (warps_total * 32) / 256;   // 2560
    emb_pool_kernel<<<blocks, 256>>>(ids_uid, ids_item, t_uid, t_item, out);
}